// round 16
// baseline (speedup 1.0000x reference)
#include <cuda_runtime.h>
#include <cuda_fp16.h>
#include <math.h>
#include <stdint.h>

typedef unsigned long long u64;
typedef unsigned int u32;
#define DINL __device__ __forceinline__

#define OUTEL  2097152            // 4*2048*256

// ---------------- scratch ----------------
static __device__ float g_Fa [32768];             // e^{sn}
static __device__ float g_Fb [32768];             // e^{0.2 sn}
static __device__ float g_Ea [32768];             // e^{ss}
static __device__ float g_Eb [32768];             // e^{0.2 ss}
static __device__ float g_epart[512];
static __device__ int   g_pcd[512];               // per-block (cntD - cntA)
static __device__ int   g_mpart[512];
static __device__ int   g_tick;
// B fragments, K-permuted, nt-paired: [bh][jc=64][256 uint4]
static __device__ uint4 g_fB4[16*64*256];

// ---------------- mma.sync m16n8k16 fp16 ----------------
DINL void mma16816(float* d, const u32* a, u32 b0, u32 b1){
    asm volatile(
        "mma.sync.aligned.m16n8k16.row.col.f32.f16.f16.f32 "
        "{%0,%1,%2,%3}, {%4,%5,%6,%7}, {%8,%9}, {%0,%1,%2,%3};"
        : "+f"(d[0]), "+f"(d[1]), "+f"(d[2]), "+f"(d[3])
        : "r"(a[0]), "r"(a[1]), "r"(a[2]), "r"(a[3]), "r"(b0), "r"(b1));
}
DINL u32 pk_h2(float p0, float p1){
    __half2 hh = __floats2half2_rn(p0, p1);
    return *(u32*)&hh;
}

// ================= kernel 1: feats GEMM + scores + fp16 pack + mask scan =================
// grid (32, 4, 4) = (ntile64, h, b), 256 threads
__global__ void __launch_bounds__(256) k_feats(const float* __restrict__ x,
                                               const float* __restrict__ W,
                                               const float* __restrict__ a_self,
                                               const float* __restrict__ a_neigh,
                                               const float* __restrict__ mask){
    __shared__ float Ws[4096];
    __shared__ float Xs[64*65];
    int b = blockIdx.z, h = blockIdx.y, it = blockIdx.x, t = threadIdx.x;
    int bh = b*4 + h;
    int L = bh*32 + it;
    if (L == 0 && t == 0) g_tick = 0;
    const float* wsrc = W + h*4096;
    const float* xsrc = x + (b*2048 + it*64)*64;
    for (int e = t; e < 4096; e += 256){
        Ws[e] = wsrc[e];
        Xs[(e >> 6)*65 + (e & 63)] = xsrc[e];
    }
    __syncthreads();
    int k = t & 63, rg = t >> 6;
    float acc[16];
    #pragma unroll
    for (int r = 0; r < 16; r++) acc[r] = 0.f;
    #pragma unroll 8
    for (int f = 0; f < 64; f++){
        float wf = Ws[f*64 + k];
        #pragma unroll
        for (int r = 0; r < 16; r++) acc[r] += Xs[(rg*16 + r)*65 + f] * wf;
    }
    __syncthreads();
    #pragma unroll
    for (int r = 0; r < 16; r++) Xs[(rg*16 + r)*65 + k] = acc[r];
    __syncthreads();

    // ---- scores ----
    int wid = t >> 5, lane = t & 31;
    float as0 = a_self[h*64 + lane],  as1 = a_self[h*64 + lane + 32];
    float an0 = a_neigh[h*64 + lane], an1 = a_neigh[h*64 + lane + 32];
    #pragma unroll
    for (int rr = 0; rr < 8; rr++){
        int row = wid*8 + rr;
        float f0 = Xs[row*65 + lane], f1 = Xs[row*65 + lane + 32];
        float ss = f0*as0 + f1*as1;
        float sn = f0*an0 + f1*an1;
        #pragma unroll
        for (int o = 16; o > 0; o >>= 1){
            ss += __shfl_xor_sync(0xffffffffu, ss, o);
            sn += __shfl_xor_sync(0xffffffffu, sn, o);
        }
        if (lane == 0){
            int gr = bh*2048 + it*64 + row;
            g_Ea[gr]  = __expf(ss);
            g_Eb[gr]  = __expf(0.2f*ss);
            g_Fa[gr]  = __expf(sn);
            g_Fb[gr]  = __expf(0.2f*sn);
        }
    }

    // ---- K-permuted nt-paired fragment pack: 512 uint4 (two jc tiles) ----
    uint4* dst = g_fB4 + ((size_t)bh*64 + it*2)*256;
    #pragma unroll
    for (int q = 0; q < 2; q++){
        int e = q*256 + t;
        int tile = e >> 8, ee = e & 255;
        int ks = ee >> 7, np = (ee >> 5) & 3, ln = ee & 31;
        int g2 = ln >> 2, tt2 = ln & 3;
        int n0 = np*16 + g2;
        int n1 = n0 + 8;
        int j0 = tile*32 + ks*16 + 4*tt2;
        u32 xx = pk_h2(Xs[j0*65 + n0],     Xs[(j0+1)*65 + n0]);
        u32 yy = pk_h2(Xs[(j0+2)*65 + n0], Xs[(j0+3)*65 + n0]);
        u32 zz = pk_h2(Xs[j0*65 + n1],     Xs[(j0+1)*65 + n1]);
        u32 ww = pk_h2(Xs[(j0+2)*65 + n1], Xs[(j0+3)*65 + n1]);
        dst[(size_t)tile*256 + ee] = make_uint4(xx, yy, zz, ww);
    }

    // ---- mask nonzero scan ----
    {
        const uint4* m4 = (const uint4*)mask + (size_t)L*8192;
        u32 v = 0;
        #pragma unroll 8
        for (int q = t; q < 8192; q += 256){
            uint4 a = m4[q];
            v |= a.x | a.y | a.z | a.w;
        }
        int any = __syncthreads_or(v != 0u);
        if (t == 0) g_mpart[L] = any;
    }
}

// ================= kernel 2: full-row fused attention GEMM + final losses =================
// grid (32,4,4): x=it (64-row tile), y=h, z=b; 128 threads = 4 warps; no main-loop barriers.
__global__ void __launch_bounds__(128, 4) k_main(const float* __restrict__ adj,
                                                 const float* __restrict__ mask,
                                                 const float* __restrict__ bias,
                                                 float* __restrict__ out){
    __shared__ float FaS[2048], FbS[2048];        // 16KB
    __shared__ float rE[4];
    __shared__ float rF[128];
    __shared__ int   rD[128];
    __shared__ int   s_last;

    int b = blockIdx.z, h = blockIdx.y, it = blockIdx.x;
    int t = threadIdx.x, wid = t >> 5, lane = t & 31;
    int g = lane >> 2, tt = lane & 3;
    int bh = b*4 + h;

    {
        const float4* fa4 = (const float4*)(g_Fa + bh*2048);
        const float4* fb4 = (const float4*)(g_Fb + bh*2048);
        #pragma unroll
        for (int q = 0; q < 4; q++){
            ((float4*)FaS)[q*128 + t] = fa4[q*128 + t];
            ((float4*)FbS)[q*128 + t] = fb4[q*128 + t];
        }
    }

    int mv = g_mpart[t] | g_mpart[t + 128] | g_mpart[t + 256] | g_mpart[t + 384];
    const bool mz = !__syncthreads_or(mv);   // also publishes FaS/FbS

    int r0 = it*64 + wid*16 + g;
    float Ea0 = g_Ea[bh*2048 + r0], Ea1 = g_Ea[bh*2048 + r0 + 8];
    float Eb0 = g_Eb[bh*2048 + r0], Eb1 = g_Eb[bh*2048 + r0 + 8];
    size_t row0 = ((size_t)(b*2048 + r0))*2048;
    size_t row1 = row0 + (size_t)8*2048;

    const uint4* fB = g_fB4 + (size_t)bh*64*256;

    float acc[8][4];
    #pragma unroll
    for (int nt = 0; nt < 8; nt++)
        #pragma unroll
        for (int r = 0; r < 4; r++) acc[nt][r] = 0.f;

    float zp0 = 0.f, zp1 = 0.f, sp0 = 0.f, sp1 = 0.f;
    int cnt = 0;                           // (cntD - cntA)

    #define LOAD_B(BF, c) do { \
        const uint4* _s = fB + (size_t)(c)*256 + lane; \
        _Pragma("unroll") \
        for (int _i = 0; _i < 8; _i++) BF[_i] = _s[_i*32]; \
    } while(0)

    #define LOAD_ADJ(R, c) do { \
        int _c0 = (c)*32 + 4*tt; \
        R[0] = *(const float4*)(adj + row0 + _c0); \
        R[1] = *(const float4*)(adj + row1 + _c0); \
        R[2] = *(const float4*)(adj + row0 + _c0 + 16); \
        R[3] = *(const float4*)(adj + row1 + _c0 + 16); \
    } while(0)

    #define COMP(AH, R, c) do { \
        _Pragma("unroll") \
        for (int _ks = 0; _ks < 2; _ks++){ \
            int _col = (c)*32 + _ks*16 + 4*tt; \
            float4 _a0 = R[_ks*2], _a1 = R[_ks*2 + 1]; \
            float4 _fa = *(const float4*)(FaS + _col); \
            float4 _fb = *(const float4*)(FbS + _col); \
            float _w00 = fmaxf(Ea0*_fa.x, Eb0*_fb.x); \
            float _w01 = fmaxf(Ea0*_fa.y, Eb0*_fb.y); \
            float _w02 = fmaxf(Ea0*_fa.z, Eb0*_fb.z); \
            float _w03 = fmaxf(Ea0*_fa.w, Eb0*_fb.w); \
            float _w10 = fmaxf(Ea1*_fa.x, Eb1*_fb.x); \
            float _w11 = fmaxf(Ea1*_fa.y, Eb1*_fb.y); \
            float _w12 = fmaxf(Ea1*_fa.z, Eb1*_fb.z); \
            float _w13 = fmaxf(Ea1*_fa.w, Eb1*_fb.w); \
            if (!mz){ \
                float4 _m0 = *(const float4*)(mask + row0 + _col); \
                float4 _m1 = *(const float4*)(mask + row1 + _col); \
                _w00 *= __expf(_m0.x); _w01 *= __expf(_m0.y); \
                _w02 *= __expf(_m0.z); _w03 *= __expf(_m0.w); \
                _w10 *= __expf(_m1.x); _w11 *= __expf(_m1.y); \
                _w12 *= __expf(_m1.z); _w13 *= __expf(_m1.w); \
            } \
            float _p00 = _a0.x*_w00, _p01 = _a0.y*_w01, _p02 = _a0.z*_w02, _p03 = _a0.w*_w03; \
            float _p10 = _a1.x*_w10, _p11 = _a1.y*_w11, _p12 = _a1.z*_w12, _p13 = _a1.w*_w13; \
            zp0 += (_w00 + _w01) + (_w02 + _w03); \
            zp1 += (_w10 + _w11) + (_w12 + _w13); \
            sp0 += (fabsf(_p00) + fabsf(_p01)) + (fabsf(_p02) + fabsf(_p03)); \
            sp1 += (fabsf(_p10) + fabsf(_p11)) + (fabsf(_p12) + fabsf(_p13)); \
            cnt += ((_p00 != 0.f) - (_a0.x != 0.f)) + ((_p01 != 0.f) - (_a0.y != 0.f)) \
                 + ((_p02 != 0.f) - (_a0.z != 0.f)) + ((_p03 != 0.f) - (_a0.w != 0.f)) \
                 + ((_p10 != 0.f) - (_a1.x != 0.f)) + ((_p11 != 0.f) - (_a1.y != 0.f)) \
                 + ((_p12 != 0.f) - (_a1.z != 0.f)) + ((_p13 != 0.f) - (_a1.w != 0.f)); \
            AH[_ks*4 + 0] = pk_h2(_p00, _p01); \
            AH[_ks*4 + 1] = pk_h2(_p10, _p11); \
            AH[_ks*4 + 2] = pk_h2(_p02, _p03); \
            AH[_ks*4 + 3] = pk_h2(_p12, _p13); \
        } \
    } while(0)

    #define MMA_CHUNK(BF, AH) do { \
        _Pragma("unroll") \
        for (int _ks = 0; _ks < 2; _ks++){ \
            _Pragma("unroll") \
            for (int _np = 0; _np < 4; _np++){ \
                uint4 _bb = BF[_ks*4 + _np]; \
                mma16816(acc[2*_np],     &AH[_ks*4], _bb.x, _bb.y); \
                mma16816(acc[2*_np + 1], &AH[_ks*4], _bb.z, _bb.w); \
            } \
        } \
    } while(0)

    float4 RA[4], RB[4];
    LOAD_ADJ(RA, 0);

    #pragma unroll 1
    for (int c = 0; c < 64; c += 2){
        uint4 BF[8];
        u32 ah[8];
        LOAD_B(BF, c);                 // covered by COMP below
        LOAD_ADJ(RB, c + 1);           // distance-1 adj prefetch
        COMP(ah, RA, c);
        MMA_CHUNK(BF, ah);
        LOAD_B(BF, c + 1);
        if (c + 2 < 64) LOAD_ADJ(RA, c + 2);
        COMP(ah, RB, c + 1);
        MMA_CHUNK(BF, ah);
    }

    // ---- full-row Z and S via quad reduce (tt) ----
    #pragma unroll
    for (int o = 1; o <= 2; o <<= 1){
        zp0 += __shfl_xor_sync(0xffffffffu, zp0, o);
        zp1 += __shfl_xor_sync(0xffffffffu, zp1, o);
        sp0 += __shfl_xor_sync(0xffffffffu, sp0, o);
        sp1 += __shfl_xor_sync(0xffffffffu, sp1, o);
    }
    float iz0 = 1.f / zp0, iz1 = 1.f / zp1;

    // ---- e_loss warp partial (quad lanes duplicate; scale by 1/4) ----
    float eterm = (sp0*iz0 + sp1*iz1) * 0.25f;
    #pragma unroll
    for (int o = 16; o > 0; o >>= 1) eterm += __shfl_xor_sync(0xffffffffu, eterm, o);
    if (lane == 0) rE[wid] = eterm;

    // ---- epilogue: normalize + bias + BN + relu ----
    const float SC = 0.9995003746877732f;   // 1/sqrt(1.001)
    size_t obase = ((size_t)(b*2048 + r0))*256 + h*64 + 2*tt;
    #pragma unroll
    for (int nt = 0; nt < 8; nt++){
        float2 bi = *(const float2*)&bias[h*64 + nt*8 + 2*tt];
        float2 o0, o1;
        o0.x = fmaxf((acc[nt][0]*iz0 + bi.x)*SC, 0.f);
        o0.y = fmaxf((acc[nt][1]*iz0 + bi.y)*SC, 0.f);
        o1.x = fmaxf((acc[nt][2]*iz1 + bi.x)*SC, 0.f);
        o1.y = fmaxf((acc[nt][3]*iz1 + bi.y)*SC, 0.f);
        *(float2*)&out[obase + nt*8]         = o0;
        *(float2*)&out[obase + nt*8 + 8*256] = o1;
    }

    // ---- deterministic block reduces ----
    rD[t] = cnt;
    __syncthreads();
    #pragma unroll
    for (int s = 64; s > 0; s >>= 1){
        if (t < s) rD[t] += rD[t + s];
        __syncthreads();
    }
    if (t == 0){
        int pb = bh*32 + it;
        g_pcd[pb] = rD[0];
        g_epart[pb] = rE[0] + rE[1] + rE[2] + rE[3];
        __threadfence();
        int r = atomicAdd(&g_tick, 1);
        s_last = (r == 511);
    }
    __syncthreads();

    // ---- last block finalizes aux losses ----
    if (s_last){
        __threadfence();
        int d = 0; float e = 0.f;
        #pragma unroll
        for (int k2 = 0; k2 < 4; k2++){
            int idx = t*4 + k2;
            d += g_pcd[idx];
            e += g_epart[idx];
        }
        rD[t] = d; rF[t] = e;
        __syncthreads();
        #pragma unroll
        for (int s = 16; s > 0; s >>= 1){
            if ((t & 31) < s){ rD[t] += rD[t + s]; rF[t] += rF[t + s]; }
            __syncthreads();
        }
        if ((t & 31) == 0){
            int bb = t >> 5;
            out[OUTEL + bb]     = (float)rD[t] * (1.f/2048.f);
            out[OUTEL + 4 + bb] = rF[t] * (1.f/2048.f);
        }
    }
    #undef LOAD_B
    #undef LOAD_ADJ
    #undef COMP
    #undef MMA_CHUNK
}

// ================= launch =================
extern "C" void kernel_launch(void* const* d_in, const int* in_sizes, int n_in,
                              void* d_out, int out_size){
    const float* x       = (const float*)d_in[0];
    const float* adj     = (const float*)d_in[1];
    const float* mask    = (const float*)d_in[2];
    const float* W       = (const float*)d_in[3];
    const float* a_self  = (const float*)d_in[4];
    const float* a_neigh = (const float*)d_in[5];
    const float* bias    = (const float*)d_in[6];
    float* out = (float*)d_out;

    k_feats <<<dim3(32, 4, 4), 256>>>(x, W, a_self, a_neigh, mask);
    k_main  <<<dim3(32, 4, 4), 128>>>(adj, mask, bias, out);
}

// round 17
// speedup vs baseline: 1.0833x; 1.0833x over previous
#include <cuda_runtime.h>
#include <cuda_fp16.h>
#include <math.h>
#include <stdint.h>

typedef unsigned long long u64;
typedef unsigned int u32;
#define DINL __device__ __forceinline__

#define OUTEL  2097152            // 4*2048*256

// ---------------- scratch ----------------
static __device__ float g_Fa [32768];             // e^{sn}
static __device__ float g_Fb [32768];             // e^{0.2 sn}
static __device__ float g_Ea [32768];             // e^{ss}
static __device__ float g_Eb [32768];             // e^{0.2 ss}
static __device__ float g_epart[512];
static __device__ int   g_pcd[512];               // per-block (cntD - cntA)
static __device__ int   g_mpart[512];
static __device__ int   g_tick;
// B fragments, K-permuted, nt-paired: [bh][jc=64][256 uint4]
static __device__ uint4 g_fB4[16*64*256];

// ---------------- mma.sync m16n8k16 fp16 ----------------
DINL void mma16816(float* d, const u32* a, u32 b0, u32 b1){
    asm volatile(
        "mma.sync.aligned.m16n8k16.row.col.f32.f16.f16.f32 "
        "{%0,%1,%2,%3}, {%4,%5,%6,%7}, {%8,%9}, {%0,%1,%2,%3};"
        : "+f"(d[0]), "+f"(d[1]), "+f"(d[2]), "+f"(d[3])
        : "r"(a[0]), "r"(a[1]), "r"(a[2]), "r"(a[3]), "r"(b0), "r"(b1));
}
DINL u32 pk_h2(float p0, float p1){
    __half2 hh = __floats2half2_rn(p0, p1);
    return *(u32*)&hh;
}

// ================= kernel 1: feats GEMM + scores + fp16 pack + mask scan =================
// grid (32, 4, 4) = (ntile64, h, b), 256 threads
__global__ void __launch_bounds__(256) k_feats(const float* __restrict__ x,
                                               const float* __restrict__ W,
                                               const float* __restrict__ a_self,
                                               const float* __restrict__ a_neigh,
                                               const float* __restrict__ mask){
    __shared__ float Ws[4096];
    __shared__ float Xs[64*65];
    int b = blockIdx.z, h = blockIdx.y, it = blockIdx.x, t = threadIdx.x;
    int bh = b*4 + h;
    int L = bh*32 + it;
    if (L == 0 && t == 0) g_tick = 0;
    const float* wsrc = W + h*4096;
    const float* xsrc = x + (b*2048 + it*64)*64;
    for (int e = t; e < 4096; e += 256){
        Ws[e] = wsrc[e];
        Xs[(e >> 6)*65 + (e & 63)] = xsrc[e];
    }
    __syncthreads();
    int k = t & 63, rg = t >> 6;
    float acc[16];
    #pragma unroll
    for (int r = 0; r < 16; r++) acc[r] = 0.f;
    #pragma unroll 8
    for (int f = 0; f < 64; f++){
        float wf = Ws[f*64 + k];
        #pragma unroll
        for (int r = 0; r < 16; r++) acc[r] += Xs[(rg*16 + r)*65 + f] * wf;
    }
    __syncthreads();
    #pragma unroll
    for (int r = 0; r < 16; r++) Xs[(rg*16 + r)*65 + k] = acc[r];
    __syncthreads();

    // ---- scores ----
    int wid = t >> 5, lane = t & 31;
    float as0 = a_self[h*64 + lane],  as1 = a_self[h*64 + lane + 32];
    float an0 = a_neigh[h*64 + lane], an1 = a_neigh[h*64 + lane + 32];
    #pragma unroll
    for (int rr = 0; rr < 8; rr++){
        int row = wid*8 + rr;
        float f0 = Xs[row*65 + lane], f1 = Xs[row*65 + lane + 32];
        float ss = f0*as0 + f1*as1;
        float sn = f0*an0 + f1*an1;
        #pragma unroll
        for (int o = 16; o > 0; o >>= 1){
            ss += __shfl_xor_sync(0xffffffffu, ss, o);
            sn += __shfl_xor_sync(0xffffffffu, sn, o);
        }
        if (lane == 0){
            int gr = bh*2048 + it*64 + row;
            g_Ea[gr]  = __expf(ss);
            g_Eb[gr]  = __expf(0.2f*ss);
            g_Fa[gr]  = __expf(sn);
            g_Fb[gr]  = __expf(0.2f*sn);
        }
    }

    // ---- K-permuted nt-paired fragment pack: 512 uint4 (two jc tiles) ----
    uint4* dst = g_fB4 + ((size_t)bh*64 + it*2)*256;
    #pragma unroll
    for (int q = 0; q < 2; q++){
        int e = q*256 + t;
        int tile = e >> 8, ee = e & 255;
        int ks = ee >> 7, np = (ee >> 5) & 3, ln = ee & 31;
        int g2 = ln >> 2, tt2 = ln & 3;
        int n0 = np*16 + g2;
        int n1 = n0 + 8;
        int j0 = tile*32 + ks*16 + 4*tt2;
        u32 xx = pk_h2(Xs[j0*65 + n0],     Xs[(j0+1)*65 + n0]);
        u32 yy = pk_h2(Xs[(j0+2)*65 + n0], Xs[(j0+3)*65 + n0]);
        u32 zz = pk_h2(Xs[j0*65 + n1],     Xs[(j0+1)*65 + n1]);
        u32 ww = pk_h2(Xs[(j0+2)*65 + n1], Xs[(j0+3)*65 + n1]);
        dst[(size_t)tile*256 + ee] = make_uint4(xx, yy, zz, ww);
    }

    // ---- mask nonzero scan ----
    {
        const uint4* m4 = (const uint4*)mask + (size_t)L*8192;
        u32 v = 0;
        #pragma unroll 8
        for (int q = t; q < 8192; q += 256){
            uint4 a = m4[q];
            v |= a.x | a.y | a.z | a.w;
        }
        int any = __syncthreads_or(v != 0u);
        if (t == 0) g_mpart[L] = any;
    }
}

// ================= kernel 2: full-row fused attention GEMM + final losses =================
// grid (32,4,4): x=it (64-row tile), y=h, z=b; 128 threads = 4 warps.
// B staged in smem (shared across warps), superchunk = 4 jc tiles, barrier per superchunk.
__global__ void __launch_bounds__(128, 4) k_main(const float* __restrict__ adj,
                                                 const float* __restrict__ mask,
                                                 const float* __restrict__ bias,
                                                 float* __restrict__ out){
    __shared__ __align__(16) uint4 BfS[2][1024];  // double-buffered superchunks (32KB)
    __shared__ float FaS[2048], FbS[2048];        // 16KB
    __shared__ float rE[4];
    __shared__ float rF[128];
    __shared__ int   rD[128];
    __shared__ int   s_last;

    int b = blockIdx.z, h = blockIdx.y, it = blockIdx.x;
    int t = threadIdx.x, wid = t >> 5, lane = t & 31;
    int g = lane >> 2, tt = lane & 3;
    int bh = b*4 + h;

    {
        const float4* fa4 = (const float4*)(g_Fa + bh*2048);
        const float4* fb4 = (const float4*)(g_Fb + bh*2048);
        #pragma unroll
        for (int q = 0; q < 4; q++){
            ((float4*)FaS)[q*128 + t] = fa4[q*128 + t];
            ((float4*)FbS)[q*128 + t] = fb4[q*128 + t];
        }
    }

    int mv = g_mpart[t] | g_mpart[t + 128] | g_mpart[t + 256] | g_mpart[t + 384];
    const bool mz = !__syncthreads_or(mv);

    int r0 = it*64 + wid*16 + g;
    float Ea0 = g_Ea[bh*2048 + r0], Ea1 = g_Ea[bh*2048 + r0 + 8];
    float Eb0 = g_Eb[bh*2048 + r0], Eb1 = g_Eb[bh*2048 + r0 + 8];
    size_t row0 = ((size_t)(b*2048 + r0))*2048;
    size_t row1 = row0 + (size_t)8*2048;

    const uint4* fB = g_fB4 + (size_t)bh*64*256;

    float acc[8][4];
    #pragma unroll
    for (int nt = 0; nt < 8; nt++)
        #pragma unroll
        for (int r = 0; r < 4; r++) acc[nt][r] = 0.f;

    float zp0 = 0.f, zp1 = 0.f, sp0 = 0.f, sp1 = 0.f;
    int cnt = 0;                           // (cntD - cntA)

    // stage superchunk sc (4 jc tiles = 1024 uint4 = 16KB)
    #define STAGE(sc) do { \
        const uint4* _s = fB + (size_t)(sc)*1024; \
        uint4* _d = BfS[(sc) & 1]; \
        _Pragma("unroll") \
        for (int _i = 0; _i < 8; _i++) _d[_i*128 + t] = _s[_i*128 + t]; \
    } while(0)

    // batched adj loads for chunk c
    #define LOAD_ADJ(R, c) do { \
        int _c0 = (c)*32 + 4*tt; \
        R[0] = *(const float4*)(adj + row0 + _c0); \
        R[1] = *(const float4*)(adj + row1 + _c0); \
        R[2] = *(const float4*)(adj + row0 + _c0 + 16); \
        R[3] = *(const float4*)(adj + row1 + _c0 + 16); \
    } while(0)

    #define COMP(AH, R, c) do { \
        _Pragma("unroll") \
        for (int _ks = 0; _ks < 2; _ks++){ \
            int _col = (c)*32 + _ks*16 + 4*tt; \
            float4 _a0 = R[_ks*2], _a1 = R[_ks*2 + 1]; \
            float4 _fa = *(const float4*)(FaS + _col); \
            float4 _fb = *(const float4*)(FbS + _col); \
            float _w00 = fmaxf(Ea0*_fa.x, Eb0*_fb.x); \
            float _w01 = fmaxf(Ea0*_fa.y, Eb0*_fb.y); \
            float _w02 = fmaxf(Ea0*_fa.z, Eb0*_fb.z); \
            float _w03 = fmaxf(Ea0*_fa.w, Eb0*_fb.w); \
            float _w10 = fmaxf(Ea1*_fa.x, Eb1*_fb.x); \
            float _w11 = fmaxf(Ea1*_fa.y, Eb1*_fb.y); \
            float _w12 = fmaxf(Ea1*_fa.z, Eb1*_fb.z); \
            float _w13 = fmaxf(Ea1*_fa.w, Eb1*_fb.w); \
            if (!mz){ \
                float4 _m0 = *(const float4*)(mask + row0 + _col); \
                float4 _m1 = *(const float4*)(mask + row1 + _col); \
                _w00 *= __expf(_m0.x); _w01 *= __expf(_m0.y); \
                _w02 *= __expf(_m0.z); _w03 *= __expf(_m0.w); \
                _w10 *= __expf(_m1.x); _w11 *= __expf(_m1.y); \
                _w12 *= __expf(_m1.z); _w13 *= __expf(_m1.w); \
            } \
            float _p00 = _a0.x*_w00, _p01 = _a0.y*_w01, _p02 = _a0.z*_w02, _p03 = _a0.w*_w03; \
            float _p10 = _a1.x*_w10, _p11 = _a1.y*_w11, _p12 = _a1.z*_w12, _p13 = _a1.w*_w13; \
            zp0 += (_w00 + _w01) + (_w02 + _w03); \
            zp1 += (_w10 + _w11) + (_w12 + _w13); \
            sp0 += (fabsf(_p00) + fabsf(_p01)) + (fabsf(_p02) + fabsf(_p03)); \
            sp1 += (fabsf(_p10) + fabsf(_p11)) + (fabsf(_p12) + fabsf(_p13)); \
            cnt += ((_p00 != 0.f) - (_a0.x != 0.f)) + ((_p01 != 0.f) - (_a0.y != 0.f)) \
                 + ((_p02 != 0.f) - (_a0.z != 0.f)) + ((_p03 != 0.f) - (_a0.w != 0.f)) \
                 + ((_p10 != 0.f) - (_a1.x != 0.f)) + ((_p11 != 0.f) - (_a1.y != 0.f)) \
                 + ((_p12 != 0.f) - (_a1.z != 0.f)) + ((_p13 != 0.f) - (_a1.w != 0.f)); \
            AH[_ks*4 + 0] = pk_h2(_p00, _p01); \
            AH[_ks*4 + 1] = pk_h2(_p10, _p11); \
            AH[_ks*4 + 2] = pk_h2(_p02, _p03); \
            AH[_ks*4 + 3] = pk_h2(_p12, _p13); \
        } \
    } while(0)

    #define MMA_CHUNK(sc, cc, AH) do { \
        const uint4* _B = BfS[(sc) & 1] + (cc)*256; \
        _Pragma("unroll") \
        for (int _ks = 0; _ks < 2; _ks++){ \
            _Pragma("unroll") \
            for (int _np = 0; _np < 4; _np++){ \
                uint4 _bb = _B[(_ks*4 + _np)*32 + lane]; \
                mma16816(acc[2*_np],     &AH[_ks*4], _bb.x, _bb.y); \
                mma16816(acc[2*_np + 1], &AH[_ks*4], _bb.z, _bb.w); \
            } \
        } \
    } while(0)

    STAGE(0);
    __syncthreads();

    #pragma unroll 1
    for (int sc = 0; sc < 16; sc++){
        if (sc + 1 < 16) STAGE(sc + 1);
        #pragma unroll
        for (int cc = 0; cc < 4; cc += 2){
            int c = sc*4 + cc;
            float4 RA[4], RB[4];
            LOAD_ADJ(RA, c);
            LOAD_ADJ(RB, c + 1);
            u32 ah[8];
            COMP(ah, RA, c);
            MMA_CHUNK(sc, cc, ah);
            COMP(ah, RB, c + 1);
            MMA_CHUNK(sc, cc + 1, ah);
        }
        __syncthreads();
    }

    // ---- full-row Z and S via quad reduce (tt) ----
    #pragma unroll
    for (int o = 1; o <= 2; o <<= 1){
        zp0 += __shfl_xor_sync(0xffffffffu, zp0, o);
        zp1 += __shfl_xor_sync(0xffffffffu, zp1, o);
        sp0 += __shfl_xor_sync(0xffffffffu, sp0, o);
        sp1 += __shfl_xor_sync(0xffffffffu, sp1, o);
    }
    float iz0 = 1.f / zp0, iz1 = 1.f / zp1;

    // ---- e_loss warp partial (quad lanes duplicate; scale by 1/4) ----
    float eterm = (sp0*iz0 + sp1*iz1) * 0.25f;
    #pragma unroll
    for (int o = 16; o > 0; o >>= 1) eterm += __shfl_xor_sync(0xffffffffu, eterm, o);
    if (lane == 0) rE[wid] = eterm;

    // ---- epilogue: normalize + bias + BN + relu ----
    const float SC = 0.9995003746877732f;   // 1/sqrt(1.001)
    size_t obase = ((size_t)(b*2048 + r0))*256 + h*64 + 2*tt;
    #pragma unroll
    for (int nt = 0; nt < 8; nt++){
        float2 bi = *(const float2*)&bias[h*64 + nt*8 + 2*tt];
        float2 o0, o1;
        o0.x = fmaxf((acc[nt][0]*iz0 + bi.x)*SC, 0.f);
        o0.y = fmaxf((acc[nt][1]*iz0 + bi.y)*SC, 0.f);
        o1.x = fmaxf((acc[nt][2]*iz1 + bi.x)*SC, 0.f);
        o1.y = fmaxf((acc[nt][3]*iz1 + bi.y)*SC, 0.f);
        *(float2*)&out[obase + nt*8]         = o0;
        *(float2*)&out[obase + nt*8 + 8*256] = o1;
    }

    // ---- deterministic block reduces ----
    rD[t] = cnt;
    __syncthreads();
    #pragma unroll
    for (int s = 64; s > 0; s >>= 1){
        if (t < s) rD[t] += rD[t + s];
        __syncthreads();
    }
    if (t == 0){
        int pb = bh*32 + it;
        g_pcd[pb] = rD[0];
        g_epart[pb] = rE[0] + rE[1] + rE[2] + rE[3];
        __threadfence();
        int r = atomicAdd(&g_tick, 1);
        s_last = (r == 511);
    }
    __syncthreads();

    // ---- last block finalizes aux losses ----
    if (s_last){
        __threadfence();
        int d = 0; float e = 0.f;
        #pragma unroll
        for (int k2 = 0; k2 < 4; k2++){
            int idx = t*4 + k2;
            d += g_pcd[idx];
            e += g_epart[idx];
        }
        rD[t] = d; rF[t] = e;
        __syncthreads();
        #pragma unroll
        for (int s = 16; s > 0; s >>= 1){
            if ((t & 31) < s){ rD[t] += rD[t + s]; rF[t] += rF[t + s]; }
            __syncthreads();
        }
        if ((t & 31) == 0){
            int bb = t >> 5;
            out[OUTEL + bb]     = (float)rD[t] * (1.f/2048.f);
            out[OUTEL + 4 + bb] = rF[t] * (1.f/2048.f);
        }
    }
    #undef STAGE
    #undef LOAD_ADJ
    #undef COMP
    #undef MMA_CHUNK
}

// ================= launch =================
extern "C" void kernel_launch(void* const* d_in, const int* in_sizes, int n_in,
                              void* d_out, int out_size){
    const float* x       = (const float*)d_in[0];
    const float* adj     = (const float*)d_in[1];
    const float* mask    = (const float*)d_in[2];
    const float* W       = (const float*)d_in[3];
    const float* a_self  = (const float*)d_in[4];
    const float* a_neigh = (const float*)d_in[5];
    const float* bias    = (const float*)d_in[6];
    float* out = (float*)d_out;

    k_feats <<<dim3(32, 4, 4), 256>>>(x, W, a_self, a_neigh, mask);
    k_main  <<<dim3(32, 4, 4), 128>>>(adj, mask, bias, out);
}